// round 10
// baseline (speedup 1.0000x reference)
#include <cuda_runtime.h>
#include <cuda_fp16.h>
#include <cstdint>

#define DEV __device__ __forceinline__

namespace {
constexpr int NPTS = 131072;
constexpr int MT = 64;        // points per CTA (2 CTAs/SM)
constexpr int THREADS = 288;  // 8 compute warps (2Mx4N, 32x64 tiles) + 1 producer warp
constexpr int CTH = 256;      // compute threads
constexpr int KC = 32;        // K chunk
constexpr int AS = 264;       // activation row stride (halves); 528B
constexpr int WS = 40;        // weight/feat row stride (halves); 80B
constexpr float TWO_PI = 6.2831853071795864769f;

constexpr int CH_H = 256 * WS;       // halves per weight chunk (10240)
constexpr uint32_t CH_B = CH_H * 2;  // 20480 bytes
constexpr int L0_CHUNKS = 17;        // K0 = 544 (515 padded)
constexpr int N_CHUNKS = L0_CHUNKS + 64;  // 81 flat chunks

constexpr int H_STRIDE = MT * AS;          // halves per CTA tile in g_h (16896)
constexpr uint32_t H_BYTES = H_STRIDE * 2; // 33792

// SMEM map (bytes) — total 112704, 2 CTAs/SM
constexpr int OFF_ACT   = 0;                 // 64*264*2 = 33792 (in-place)
constexpr int OFF_WRING = 33792;             // 3 * 20480 = 61440
constexpr int OFF_UNION = 95232;             // L0: sx+sB | heads: Wc2+Wn2 (4096)
constexpr int OFF_SX    = OFF_UNION;
constexpr int OFF_SB    = OFF_UNION + 1024;
constexpr int OFF_WC2   = OFF_UNION;
constexpr int OFF_WN2   = OFF_UNION + 3072;
constexpr int OFF_FEAT  = 99328;             // 2 * 5120
constexpr int OFF_BIAS  = 109568;            // 2 x 1024 (double-buffered)
constexpr int OFF_OUTAC = 111616;            // 1024 (64*4 floats)
constexpr int OFF_FULL  = 112640;            // 3 x 8
constexpr int OFF_EMPTY = 112664;            // 3 x 8
constexpr int OFF_HBAR  = 112688;            // 8
constexpr int SMEM_BYTES = 112704;
}

// Weight images, flat: chunk i at g_Wt + i*CH_H.
__device__ __half g_Wt[(size_t)N_CHUNKS * CH_H];
// h spill (layer-4 output), per-CTA tile in padded AS layout (padding never consumed)
__device__ __half g_h[(size_t)(NPTS / MT) * H_STRIDE];

// ---------------- helpers ----------------
DEV uint32_t smem_u32(const void* p) {
  uint32_t a;
  asm("{ .reg .u64 t; cvta.to.shared.u64 t, %1; cvt.u32.u64 %0, t; }" : "=r"(a) : "l"(p));
  return a;
}
#define MBAR_INIT(mb, c) \
  asm volatile("mbarrier.init.shared.b64 [%0], %1;" :: "r"(mb), "r"(c) : "memory")
#define MBAR_ARRIVE(mb) \
  asm volatile("mbarrier.arrive.shared.b64 _, [%0];" :: "r"(mb) : "memory")
#define MBAR_WAIT(mb, ph) do {                                                        \
  uint32_t _m = (mb), _p = (uint32_t)(ph), _d;                                        \
  asm volatile("{ .reg .pred p; mbarrier.try_wait.parity.acquire.cta.shared::cta.b64 p, [%1], %2; selp.b32 %0,1,0,p; }" \
               : "=r"(_d) : "r"(_m), "r"(_p) : "memory");                             \
  if (!_d) {                                                                          \
    asm volatile("{ .reg .pred P1; WL%=: mbarrier.try_wait.parity.acquire.cta.shared::cta.b64 P1, [%0], %1, 0x989680; @P1 bra.uni WD%=; bra.uni WL%=; WD%=: }" \
                 :: "r"(_m), "r"(_p) : "memory");                                     \
  }                                                                                   \
} while (0)

DEV void barsync() { asm volatile("bar.sync 1, 256;" ::: "memory"); }  // compute warps only

DEV void issue_bulk(uint32_t dst32, const void* src, uint32_t nbytes, uint32_t mbar) {
  asm volatile("mbarrier.arrive.expect_tx.shared.b64 _, [%0], %1;"
               :: "r"(mbar), "r"(nbytes) : "memory");
  asm volatile(
      "cp.async.bulk.shared::cta.global.mbarrier::complete_tx::bytes [%0], [%1], %2, [%3];"
      :: "r"(dst32), "l"(src), "r"(nbytes), "r"(mbar) : "memory");
}

DEV void ldsm4(uint32_t* r, uint32_t addr) {
  asm volatile("ldmatrix.sync.aligned.m8n8.x4.shared.b16 {%0,%1,%2,%3}, [%4];"
               : "=r"(r[0]), "=r"(r[1]), "=r"(r[2]), "=r"(r[3]) : "r"(addr));
}
DEV void mma16816(float* d, const uint32_t* a, uint32_t b0, uint32_t b1) {
  asm volatile(
      "mma.sync.aligned.m16n8k16.row.col.f32.f16.f16.f32 "
      "{%0,%1,%2,%3}, {%4,%5,%6,%7}, {%8,%9}, {%0,%1,%2,%3};\n"
      : "+f"(d[0]), "+f"(d[1]), "+f"(d[2]), "+f"(d[3])
      : "r"(a[0]), "r"(a[1]), "r"(a[2]), "r"(a[3]), "r"(b0), "r"(b1));
}
DEV float frelu(float v) { return fmaxf(v, 0.0f); }
DEV uint32_t pack2(float a, float b) {
  __half2 h = __floats2half2_rn(a, b);
  return *reinterpret_cast<uint32_t*>(&h);
}

// ---------------- prep: pack weights into SMEM-image layout ----------------
__global__ void prep_weights(const float* W0, const float* W1, const float* W2,
                             const float* W3, const float* W4, const float* Wc0,
                             const float* Wc1, const float* Wn0, const float* Wn1) {
  int e = blockIdx.x * blockDim.x + threadIdx.x;
  constexpr int TOTAL = N_CHUNKS * CH_H;
  if (e >= TOTAL) return;
  int chunk = e / CH_H, r = e % CH_H, n = r / WS, kk = r % WS;
  float v = 0.0f;
  if (kk < KC) {
    if (chunk < L0_CHUNKS) {
      int k = chunk * KC + kk;
      if (k < 515) v = W0[k * 256 + n];
    } else {
      int c2 = chunk - L0_CHUNKS;
      int l = c2 >> 3, k = (c2 & 7) * KC + kk;
      const float* Ws[8] = {W1, W2, W3, W4, Wc0, Wc1, Wn0, Wn1};
      v = Ws[l][k * 256 + n];
    }
  }
  g_Wt[e] = __float2half(v);
}

// ---------------- fused kernel ----------------
struct Params {
  const float *x, *B;
  const float *b0, *b1, *b2, *b3, *b4, *bc0, *bc1, *bc2, *bn0, *bn1, *bn2;
  const float *Wc2, *Wn2;
  const int* t;
  float* out;
};

struct Ctx {
  char* smem;
  uint32_t act32, wring32, feat32, full32, empty32;
  int tid, wm, wn, lrow, lk, grp, qp, lane;
};

// Layer-0 feature chunk: per-thread column kk fixed; Cody-Waite reduction + MUFU.
DEV void gen_feat(const Ctx& cx, int c, float tot) {
  const float* sx = (const float*)(cx.smem + OFF_SX);
  const float* sB = (const float*)(cx.smem + OFF_SB);
  __half* dst = (__half*)(cx.smem + OFF_FEAT + (c & 1) * 5120);
  const int kk = cx.tid & 31;
  const int mb = cx.tid >> 5;  // 0..7; m = mb + i*8
  const int kg = c * KC + kk;
  if (kg >= 3 && kg < 515) {
    const bool issin = kg < 259;
    const int j = issin ? (kg - 3) : (kg - 259);
    const float Bx = sB[j], By = sB[256 + j], Bz = sB[512 + j];
    const float a = fminf(fmaxf(tot - (float)j, 0.0f), 1.0f);
#pragma unroll
    for (int i = 0; i < 8; i++) {
      const int m = mb + i * 8;
      float px = sx[m * 4] * Bx;
      px = fmaf(sx[m * 4 + 1], By, px);
      px = fmaf(sx[m * 4 + 2], Bz, px);
      float arg = px * TWO_PI;
      float qf = rintf(arg * 0.3183098861837907f);
      float r = fmaf(qf, -3.1414794921875f, arg);
      r = fmaf(qf, -1.1315941810607910156e-4f, r);
      r = fmaf(qf, -1.9841872589410058936e-9f, r);
      float v = issin ? __sinf(r) : __cosf(r);
      if (((int)qf) & 1) v = -v;
      dst[m * WS + kk] = __float2half(v * a);
    }
  } else {
    const bool isx = (kg < 3);
#pragma unroll
    for (int i = 0; i < 8; i++) {
      const int m = mb + i * 8;
      dst[m * WS + kk] = __float2half(isx ? sx[m * 4 + kg] : 0.0f);
    }
  }
}

DEV void chunk_mma(const Ctx& cx, uint32_t aBase, int ast, int kb, uint32_t wslot,
                   float acc[2][8][4]) {
  const uint32_t aA0 = aBase + ((cx.wm * 32 + cx.lrow) * ast + kb + cx.lk) * 2;
  const uint32_t bA0 = wslot + ((cx.wn * 64 + cx.lrow) * WS + cx.lk) * 2;
#pragma unroll
  for (int ks = 0; ks < KC; ks += 16) {
    uint32_t a0[4], a1[4];
    ldsm4(a0, aA0 + ks * 2);
    ldsm4(a1, aA0 + ks * 2 + 16 * ast * 2);
#pragma unroll
    for (int np = 0; np < 4; np++) {
      uint32_t bb[4];
      ldsm4(bb, bA0 + ks * 2 + np * (16 * WS * 2));
      mma16816(acc[0][2 * np],     a0, bb[0], bb[2]);
      mma16816(acc[0][2 * np + 1], a0, bb[1], bb[3]);
      mma16816(acc[1][2 * np],     a1, bb[0], bb[2]);
      mma16816(acc[1][2 * np + 1], a1, bb[1], bb[3]);
    }
  }
}

// MODE 0: act in-place. MODE 1: dot Wc2 -> outac. MODE 2: dot Wn2 -> outac.
template <int MODE, bool SAVEH>
__device__ __noinline__ void layerSq(const Ctx& cx, int base, const float* sbias,
                                     __half* gh) {
  float* outac = (float*)(cx.smem + OFF_OUTAC);
  __half* act = (__half*)(cx.smem + OFF_ACT);

  float acc[2][8][4];
#pragma unroll
  for (int a = 0; a < 2; a++)
#pragma unroll
    for (int b = 0; b < 8; b++)
#pragma unroll
      for (int d = 0; d < 4; d++) acc[a][b][d] = 0.0f;

  for (int c = 0; c < 8; c++) {
    const int g = base + c;
    const int s = g % 3;
    MBAR_WAIT(cx.full32 + s * 8, (g / 3) & 1);
    chunk_mma(cx, cx.act32, AS, c * KC, cx.wring32 + s * CH_B, acc);
    if (cx.lane == 0) MBAR_ARRIVE(cx.empty32 + s * 8);
  }
  barsync();  // in-place: all act reads done before epilogue writes

  if (MODE == 0) {
#pragma unroll
    for (int mt = 0; mt < 2; mt++) {
      const int r0 = cx.wm * 32 + mt * 16 + cx.grp;
#pragma unroll
      for (int nt = 0; nt < 8; nt++) {
        const int col = cx.wn * 64 + nt * 8 + cx.qp * 2;
        float bx = sbias[col], by = sbias[col + 1];
        uint32_t lo = pack2(frelu(acc[mt][nt][0] + bx), frelu(acc[mt][nt][1] + by));
        uint32_t hi = pack2(frelu(acc[mt][nt][2] + bx), frelu(acc[mt][nt][3] + by));
        *(uint32_t*)(act + r0 * AS + col) = lo;
        *(uint32_t*)(act + (r0 + 8) * AS + col) = hi;
        if (SAVEH) {
          *(uint32_t*)(gh + r0 * AS + col) = lo;
          *(uint32_t*)(gh + (r0 + 8) * AS + col) = hi;
        }
      }
    }
  } else {
    const float* sWc2 = (const float*)(cx.smem + OFF_WC2);
    const float* sWn2 = (const float*)(cx.smem + OFF_WN2);
    constexpr int NJ = (MODE == 1) ? 3 : 1;
    float part[2][2][NJ];
#pragma unroll
    for (int a = 0; a < 2; a++)
#pragma unroll
      for (int b = 0; b < 2; b++)
#pragma unroll
        for (int j = 0; j < NJ; j++) part[a][b][j] = 0.0f;
#pragma unroll
    for (int mt = 0; mt < 2; mt++)
#pragma unroll
      for (int nt = 0; nt < 8; nt++) {
        const int col = cx.wn * 64 + nt * 8 + cx.qp * 2;
        float bx = sbias[col], by = sbias[col + 1];
        float v0 = frelu(acc[mt][nt][0] + bx), v1 = frelu(acc[mt][nt][1] + by);
        float v2 = frelu(acc[mt][nt][2] + bx), v3 = frelu(acc[mt][nt][3] + by);
#pragma unroll
        for (int j = 0; j < NJ; j++) {
          float w0 = (MODE == 1) ? sWc2[col * 3 + j] : sWn2[col];
          float w1 = (MODE == 1) ? sWc2[(col + 1) * 3 + j] : sWn2[col + 1];
          part[mt][0][j] += v0 * w0 + v1 * w1;
          part[mt][1][j] += v2 * w0 + v3 * w1;
        }
      }
#pragma unroll
    for (int mt = 0; mt < 2; mt++)
#pragma unroll
      for (int rh = 0; rh < 2; rh++)
#pragma unroll
        for (int j = 0; j < NJ; j++) {
          float v = part[mt][rh][j];
          v += __shfl_xor_sync(0xffffffffu, v, 1);
          v += __shfl_xor_sync(0xffffffffu, v, 2);
          if (cx.qp == 0)
            atomicAdd(&outac[(cx.wm * 32 + mt * 16 + rh * 8 + cx.grp) * 4 + j], v);
        }
  }
  barsync();  // layer boundary
}

__global__ void __launch_bounds__(THREADS, 2) fused_mlp(Params p) {
  extern __shared__ char smem[];
  Ctx cx;
  cx.smem = smem;
  cx.tid = threadIdx.x;
  cx.lane = cx.tid & 31;
  const int wid = cx.tid >> 5;
  cx.wm = (wid >> 2) & 1; cx.wn = wid & 3;
  cx.lrow = cx.lane & 15; cx.lk = (cx.lane >> 4) << 3;
  cx.grp = cx.lane >> 2; cx.qp = cx.lane & 3;
  cx.act32 = smem_u32(smem + OFF_ACT);
  cx.wring32 = smem_u32(smem + OFF_WRING);
  cx.feat32 = smem_u32(smem + OFF_FEAT);
  cx.full32 = smem_u32(smem + OFF_FULL);
  cx.empty32 = smem_u32(smem + OFF_EMPTY);
  const uint32_t hbar32 = smem_u32(smem + OFF_HBAR);

  const int m0 = blockIdx.x * MT;
  __half* gh = g_h + (size_t)blockIdx.x * H_STRIDE;
  float* sx = (float*)(smem + OFF_SX);
  float* sB = (float*)(smem + OFF_SB);
  float* sb0 = (float*)(smem + OFF_BIAS);
  float* sb1 = (float*)(smem + OFF_BIAS + 1024);
  float* outac = (float*)(smem + OFF_OUTAC);
  __half* act = (__half*)(smem + OFF_ACT);

  if (cx.tid == 0) {
#pragma unroll
    for (int s = 0; s < 3; s++) {
      MBAR_INIT(cx.full32 + s * 8, 1);
      MBAR_INIT(cx.empty32 + s * 8, 8);
    }
    MBAR_INIT(hbar32, 1);
  }
  if (cx.tid < 192) {
    int m = cx.tid / 3, d = cx.tid - m * 3;
    sx[m * 4 + d] = p.x[(m0 + m) * 3 + d];
  }
  for (int i = cx.tid; i < 768; i += THREADS) sB[i] = p.B[i];
  if (cx.tid < 256) { sb0[cx.tid] = p.b0[cx.tid]; sb1[cx.tid] = p.b1[cx.tid]; }
  if (cx.tid < 256) outac[cx.tid] = 0.0f;
  __syncthreads();  // all 288 threads; LAST full-block barrier

  if (wid == 8) {  // ---- producer warp ----
    if (cx.lane == 0) {
      for (int i = 0; i < N_CHUNKS; i++) {
        int s = i % 3;
        MBAR_WAIT(cx.empty32 + s * 8, 1 ^ ((i / 3) & 1));  // first waits pass
        issue_bulk(cx.wring32 + s * CH_B, g_Wt + (size_t)i * CH_H, CH_B, cx.full32 + s * 8);
      }
    }
    return;
  }

  // ---- consumer (8 compute warps) ----
  int tbits = *p.t;
  float tval = (tbits >= 0 && tbits < (1 << 20)) ? (float)tbits : __int_as_float(tbits);
  const float tot = tval * (6000.0f / 512.0f);  // t / TAU

  // Layer 0: 17 chunks, on-the-fly features (double-buffered)
  {
    float acc[2][8][4];
#pragma unroll
    for (int a = 0; a < 2; a++)
#pragma unroll
      for (int b = 0; b < 8; b++)
#pragma unroll
        for (int d = 0; d < 4; d++) acc[a][b][d] = 0.0f;
    gen_feat(cx, 0, tot);
    for (int c = 0; c < L0_CHUNKS; c++) {
      barsync();  // feat buffer handoff
      const int s = c % 3;
      MBAR_WAIT(cx.full32 + s * 8, (c / 3) & 1);
      chunk_mma(cx, cx.feat32 + (c & 1) * 5120, WS, 0, cx.wring32 + s * CH_B, acc);
      if (cx.lane == 0) MBAR_ARRIVE(cx.empty32 + s * 8);
      if (c + 1 < L0_CHUNKS) gen_feat(cx, c + 1, tot);
    }
    // epilogue -> act (bias b0)
#pragma unroll
    for (int mt = 0; mt < 2; mt++) {
      const int r0 = cx.wm * 32 + mt * 16 + cx.grp;
#pragma unroll
      for (int nt = 0; nt < 8; nt++) {
        const int col = cx.wn * 64 + nt * 8 + cx.qp * 2;
        float bx = sb0[col], by = sb0[col + 1];
        *(uint32_t*)(act + r0 * AS + col) =
            pack2(frelu(acc[mt][nt][0] + bx), frelu(acc[mt][nt][1] + by));
        *(uint32_t*)(act + (r0 + 8) * AS + col) =
            pack2(frelu(acc[mt][nt][2] + bx), frelu(acc[mt][nt][3] + by));
      }
    }
    barsync();
  }

  // overlay head-final weights (sx/sB/feat dead) + bias pipeline
  {
    float* sWc2 = (float*)(smem + OFF_WC2);
    float* sWn2 = (float*)(smem + OFF_WN2);
    for (int i = cx.tid; i < 768; i += CTH) sWc2[i] = p.Wc2[i];
    if (cx.tid < 256) sWn2[cx.tid] = p.Wn2[cx.tid];
  }

  if (cx.tid < 256) sb0[cx.tid] = p.b2[cx.tid];
  layerSq<0, false>(cx, 17, sb1, nullptr);  // l1 (b1)
  if (cx.tid < 256) sb1[cx.tid] = p.b3[cx.tid];
  layerSq<0, false>(cx, 25, sb0, nullptr);  // l2 (b2)
  if (cx.tid < 256) sb0[cx.tid] = p.b4[cx.tid];
  layerSq<0, false>(cx, 33, sb1, nullptr);  // l3 (b3)
  if (cx.tid < 256) sb1[cx.tid] = p.bc0[cx.tid];
  layerSq<0, true >(cx, 41, sb0, gh);       // l4 (b4) -> h to act + g_h
  if (cx.tid < 256) sb0[cx.tid] = p.bc1[cx.tid];
  layerSq<0, false>(cx, 49, sb1, nullptr);  // l5 (bc0), overwrites h in act
  if (cx.tid < 256) sb1[cx.tid] = p.bn0[cx.tid];
  layerSq<1, false>(cx, 57, sb0, nullptr);  // l6 (bc1), color dot
  if (cx.tid < 192) {
    int m = cx.tid / 3, j = cx.tid - m * 3;
    float v = outac[m * 4 + j];
    outac[m * 4 + j] = 0.0f;  // read-side zero for displacement head
    p.out[(m0 + m) * 3 + j] = tanhf(v + p.bc2[j]) * 0.5f;
  }
  // restore h from g_h into act (act is free after l6's trailing barsync)
  if (cx.tid == 0) {
    asm volatile("fence.proxy.async;" ::: "memory");  // order l4's STGs before TMA read
    issue_bulk(cx.act32, gh, H_BYTES, hbar32);
  }
  MBAR_WAIT(hbar32, 0);
  barsync();
  if (cx.tid < 256) sb0[cx.tid] = p.bn1[cx.tid];
  layerSq<0, false>(cx, 65, sb1, nullptr);  // l7 (bn0)
  layerSq<2, false>(cx, 73, sb0, nullptr);  // l8 (bn1), displacement dot
  if (cx.tid < 64)
    p.out[3 * NPTS + m0 + cx.tid] = tanhf(outac[cx.tid * 4] + p.bn2[0]) * 0.1f;
}

extern "C" void kernel_launch(void* const* d_in, const int* in_sizes, int n_in,
                              void* d_out, int out_size) {
  int i = 0;
  const float* x = (const float*)d_in[i++];
  const float* B = (const float*)d_in[i++];
  const void* tp = nullptr;
  if (in_sizes[2] == 1) tp = d_in[i++];  // dict order: t at index 2
  const float *W[11], *bias[11];
  for (int j = 0; j < 11; j++) {
    W[j] = (const float*)d_in[i++];
    bias[j] = (const float*)d_in[i++];
  }
  if (!tp && i < n_in) tp = d_in[i++];

  cudaFuncSetAttribute(fused_mlp, cudaFuncAttributeMaxDynamicSharedMemorySize, SMEM_BYTES);

  constexpr int TOTAL = N_CHUNKS * CH_H;
  prep_weights<<<(TOTAL + 255) / 256, 256>>>(W[0], W[1], W[2], W[3], W[4],
                                             W[5], W[6], W[8], W[9]);

  Params p;
  p.x = x; p.B = B;
  p.b0 = bias[0]; p.b1 = bias[1]; p.b2 = bias[2]; p.b3 = bias[3]; p.b4 = bias[4];
  p.bc0 = bias[5]; p.bc1 = bias[6]; p.bc2 = bias[7];
  p.bn0 = bias[8]; p.bn1 = bias[9]; p.bn2 = bias[10];
  p.Wc2 = W[7]; p.Wn2 = W[10];
  p.t = (const int*)tp;
  p.out = (float*)d_out;

  fused_mlp<<<NPTS / MT, THREADS, SMEM_BYTES>>>(p);
}

// round 11
// speedup vs baseline: 1.1686x; 1.1686x over previous
#include <cuda_runtime.h>
#include <cuda_fp16.h>
#include <cstdint>

#define DEV __device__ __forceinline__

namespace {
constexpr int NPTS = 131072;
constexpr int MT = 128;       // points per CTA
constexpr int THREADS = 544;  // 16 compute warps (4Mx4N) + 1 producer warp
constexpr int CTH = 512;      // compute threads
constexpr int KC = 64;        // K chunk (doubled)
constexpr int AS = 264;       // activation row stride (halves); 528B
constexpr int WS = 72;        // weight/feat row stride (halves); 144B (16 mod 128 -> conflict-free)
constexpr float TWO_PI = 6.2831853071795864769f;

constexpr int CH_H = 256 * WS;       // halves per weight chunk (18432)
constexpr uint32_t CH_B = CH_H * 2;  // 36864 bytes
constexpr int L0_CHUNKS = 9;         // K0 = 576 (515 padded)
constexpr int N_CHUNKS = L0_CHUNKS + 32;  // 41 flat chunks (8 layers x 4)

constexpr int H_STRIDE = MT * AS;          // halves per CTA h tile (33792)
constexpr uint32_t H_BYTES = H_STRIDE * 2; // 67584

// SMEM map (bytes)
constexpr int OFF_ACT   = 0;                 // 128*264*2 = 67584 (in-place; feat overlaid)
constexpr int FEAT_SZ   = 128 * WS * 2;      // 18432 per feat buffer (x2, inside act region)
constexpr int OFF_WRING = 67584;             // 4 * 36864 = 147456
constexpr int OFF_UNION = 215040;            // L0: sx+sB | heads: Wc2+Wn2
constexpr int OFF_SX    = OFF_UNION;         // 2048
constexpr int OFF_SB    = OFF_UNION + 2048;  // 3072
constexpr int OFF_WC2   = OFF_UNION;         // 3072
constexpr int OFF_WN2   = OFF_UNION + 3072;  // 1024
constexpr int OFF_BIAS  = 220160;            // 2 x 1024
constexpr int OFF_OUTAC = 222208;            // 2048
constexpr int OFF_FULL  = 224256;            // 4 x 8
constexpr int OFF_EMPTY = 224288;            // 4 x 8
constexpr int OFF_HBAR  = 224320;            // 8
constexpr int SMEM_BYTES = 224384;
}

// Weight images, flat: chunk i at g_Wt + i*CH_H.
__device__ __half g_Wt[(size_t)N_CHUNKS * CH_H];
// h spill (layer-4 output), per-CTA tile in padded AS layout
__device__ __half g_h[(size_t)(NPTS / MT) * H_STRIDE];

// ---------------- helpers ----------------
DEV uint32_t smem_u32(const void* p) {
  uint32_t a;
  asm("{ .reg .u64 t; cvta.to.shared.u64 t, %1; cvt.u32.u64 %0, t; }" : "=r"(a) : "l"(p));
  return a;
}
#define MBAR_INIT(mb, c) \
  asm volatile("mbarrier.init.shared.b64 [%0], %1;" :: "r"(mb), "r"(c) : "memory")
#define MBAR_ARRIVE(mb) \
  asm volatile("mbarrier.arrive.shared.b64 _, [%0];" :: "r"(mb) : "memory")
#define MBAR_WAIT(mb, ph) do {                                                        \
  uint32_t _m = (mb), _p = (uint32_t)(ph), _d;                                        \
  asm volatile("{ .reg .pred p; mbarrier.try_wait.parity.acquire.cta.shared::cta.b64 p, [%1], %2; selp.b32 %0,1,0,p; }" \
               : "=r"(_d) : "r"(_m), "r"(_p) : "memory");                             \
  if (!_d) {                                                                          \
    asm volatile("{ .reg .pred P1; WL%=: mbarrier.try_wait.parity.acquire.cta.shared::cta.b64 P1, [%0], %1, 0x989680; @P1 bra.uni WD%=; bra.uni WL%=; WD%=: }" \
                 :: "r"(_m), "r"(_p) : "memory");                                     \
  }                                                                                   \
} while (0)

DEV void barsync() { asm volatile("bar.sync 1, 512;" ::: "memory"); }  // compute warps only

DEV void issue_bulk(uint32_t dst32, const void* src, uint32_t nbytes, uint32_t mbar) {
  asm volatile("mbarrier.arrive.expect_tx.shared.b64 _, [%0], %1;"
               :: "r"(mbar), "r"(nbytes) : "memory");
  asm volatile(
      "cp.async.bulk.shared::cta.global.mbarrier::complete_tx::bytes [%0], [%1], %2, [%3];"
      :: "r"(dst32), "l"(src), "r"(nbytes), "r"(mbar) : "memory");
}

DEV void ldsm4(uint32_t* r, uint32_t addr) {
  asm volatile("ldmatrix.sync.aligned.m8n8.x4.shared.b16 {%0,%1,%2,%3}, [%4];"
               : "=r"(r[0]), "=r"(r[1]), "=r"(r[2]), "=r"(r[3]) : "r"(addr));
}
DEV void mma16816(float* d, const uint32_t* a, uint32_t b0, uint32_t b1) {
  asm volatile(
      "mma.sync.aligned.m16n8k16.row.col.f32.f16.f16.f32 "
      "{%0,%1,%2,%3}, {%4,%5,%6,%7}, {%8,%9}, {%0,%1,%2,%3};\n"
      : "+f"(d[0]), "+f"(d[1]), "+f"(d[2]), "+f"(d[3])
      : "r"(a[0]), "r"(a[1]), "r"(a[2]), "r"(a[3]), "r"(b0), "r"(b1));
}
DEV float frelu(float v) { return fmaxf(v, 0.0f); }
DEV uint32_t pack2(float a, float b) {
  __half2 h = __floats2half2_rn(a, b);
  return *reinterpret_cast<uint32_t*>(&h);
}

// ---------------- prep: pack weights into SMEM-image layout ----------------
__global__ void prep_weights(const float* W0, const float* W1, const float* W2,
                             const float* W3, const float* W4, const float* Wc0,
                             const float* Wc1, const float* Wn0, const float* Wn1) {
  int e = blockIdx.x * blockDim.x + threadIdx.x;
  constexpr int TOTAL = N_CHUNKS * CH_H;
  if (e >= TOTAL) return;
  int chunk = e / CH_H, r = e % CH_H, n = r / WS, kk = r % WS;
  float v = 0.0f;
  if (kk < KC) {
    if (chunk < L0_CHUNKS) {
      int k = chunk * KC + kk;
      if (k < 515) v = W0[k * 256 + n];
    } else {
      int c2 = chunk - L0_CHUNKS;
      int l = c2 >> 2, k = (c2 & 3) * KC + kk;
      const float* Ws[8] = {W1, W2, W3, W4, Wc0, Wc1, Wn0, Wn1};
      v = Ws[l][k * 256 + n];
    }
  }
  g_Wt[e] = __float2half(v);
}

// ---------------- fused kernel ----------------
struct Params {
  const float *x, *B;
  const float *b0, *b1, *b2, *b3, *b4, *bc0, *bc1, *bc2, *bn0, *bn1, *bn2;
  const float *Wc2, *Wn2;
  const int* t;
  float* out;
};

struct Ctx {
  char* smem;
  uint32_t act32, wring32, full32, empty32;
  int tid, wm, wn, lrow, lk, grp, qp, lane;
};

// Layer-0 feature chunk: per-thread column kk fixed; Cody-Waite reduction + MUFU.
// Feat buffers live INSIDE the act region (disjoint lifetime with act contents).
DEV void gen_feat(const Ctx& cx, int c, float tot) {
  const float* sx = (const float*)(cx.smem + OFF_SX);
  const float* sB = (const float*)(cx.smem + OFF_SB);
  __half* dst = (__half*)(cx.smem + OFF_ACT + (c & 1) * FEAT_SZ);
  const int kk = cx.tid & 63;
  const int mb = cx.tid >> 6;  // 0..7; m = mb + i*8
  const int kg = c * KC + kk;
  if (kg >= 3 && kg < 515) {
    const bool issin = kg < 259;
    const int j = issin ? (kg - 3) : (kg - 259);
    const float Bx = sB[j], By = sB[256 + j], Bz = sB[512 + j];
    const float a = fminf(fmaxf(tot - (float)j, 0.0f), 1.0f);
#pragma unroll
    for (int i = 0; i < 16; i++) {
      const int m = mb + i * 8;
      float px = sx[m * 4] * Bx;
      px = fmaf(sx[m * 4 + 1], By, px);
      px = fmaf(sx[m * 4 + 2], Bz, px);
      float arg = px * TWO_PI;
      float qf = rintf(arg * 0.3183098861837907f);
      float r = fmaf(qf, -3.1414794921875f, arg);
      r = fmaf(qf, -1.1315941810607910156e-4f, r);
      r = fmaf(qf, -1.9841872589410058936e-9f, r);
      float v = issin ? __sinf(r) : __cosf(r);
      if (((int)qf) & 1) v = -v;
      dst[m * WS + kk] = __float2half(v * a);
    }
  } else {
    const bool isx = (kg < 3);
#pragma unroll
    for (int i = 0; i < 16; i++) {
      const int m = mb + i * 8;
      dst[m * WS + kk] = __float2half(isx ? sx[m * 4 + kg] : 0.0f);
    }
  }
}

DEV void chunk_mma(const Ctx& cx, uint32_t aBase, int ast, int kb, uint32_t wslot,
                   float acc[2][8][4]) {
  const uint32_t aA0 = aBase + ((cx.wm * 32 + cx.lrow) * ast + kb + cx.lk) * 2;
  const uint32_t bA0 = wslot + ((cx.wn * 64 + cx.lrow) * WS + cx.lk) * 2;
#pragma unroll
  for (int ks = 0; ks < KC; ks += 16) {
    uint32_t a0[4], a1[4];
    ldsm4(a0, aA0 + ks * 2);
    ldsm4(a1, aA0 + ks * 2 + 16 * ast * 2);
#pragma unroll
    for (int np = 0; np < 4; np++) {
      uint32_t bb[4];
      ldsm4(bb, bA0 + ks * 2 + np * (16 * WS * 2));
      mma16816(acc[0][2 * np],     a0, bb[0], bb[2]);
      mma16816(acc[0][2 * np + 1], a0, bb[1], bb[3]);
      mma16816(acc[1][2 * np],     a1, bb[0], bb[2]);
      mma16816(acc[1][2 * np + 1], a1, bb[1], bb[3]);
    }
  }
}

// MODE 0: act in-place. MODE 1: dot Wc2 -> outac. MODE 2: dot Wn2 -> outac.
template <int MODE, bool SAVEH>
__device__ __noinline__ void layerSq(const Ctx& cx, int base, const float* sbias,
                                     __half* gh) {
  float* outac = (float*)(cx.smem + OFF_OUTAC);
  __half* act = (__half*)(cx.smem + OFF_ACT);

  float acc[2][8][4];
#pragma unroll
  for (int a = 0; a < 2; a++)
#pragma unroll
    for (int b = 0; b < 8; b++)
#pragma unroll
      for (int d = 0; d < 4; d++) acc[a][b][d] = 0.0f;

  for (int c = 0; c < 4; c++) {
    const int g = base + c;
    const int s = g & 3;
    MBAR_WAIT(cx.full32 + s * 8, (g >> 2) & 1);
    chunk_mma(cx, cx.act32, AS, c * KC, cx.wring32 + s * CH_B, acc);
    if (cx.lane == 0) MBAR_ARRIVE(cx.empty32 + s * 8);
  }
  barsync();  // in-place: all act reads done before epilogue writes

  if (MODE == 0) {
#pragma unroll
    for (int mt = 0; mt < 2; mt++) {
      const int r0 = cx.wm * 32 + mt * 16 + cx.grp;
#pragma unroll
      for (int nt = 0; nt < 8; nt++) {
        const int col = cx.wn * 64 + nt * 8 + cx.qp * 2;
        float bx = sbias[col], by = sbias[col + 1];
        uint32_t lo = pack2(frelu(acc[mt][nt][0] + bx), frelu(acc[mt][nt][1] + by));
        uint32_t hi = pack2(frelu(acc[mt][nt][2] + bx), frelu(acc[mt][nt][3] + by));
        *(uint32_t*)(act + r0 * AS + col) = lo;
        *(uint32_t*)(act + (r0 + 8) * AS + col) = hi;
        if (SAVEH) {
          *(uint32_t*)(gh + r0 * AS + col) = lo;
          *(uint32_t*)(gh + (r0 + 8) * AS + col) = hi;
        }
      }
    }
  } else {
    const float* sWc2 = (const float*)(cx.smem + OFF_WC2);
    const float* sWn2 = (const float*)(cx.smem + OFF_WN2);
    constexpr int NJ = (MODE == 1) ? 3 : 1;
    float part[2][2][NJ];
#pragma unroll
    for (int a = 0; a < 2; a++)
#pragma unroll
      for (int b = 0; b < 2; b++)
#pragma unroll
        for (int j = 0; j < NJ; j++) part[a][b][j] = 0.0f;
#pragma unroll
    for (int mt = 0; mt < 2; mt++)
#pragma unroll
      for (int nt = 0; nt < 8; nt++) {
        const int col = cx.wn * 64 + nt * 8 + cx.qp * 2;
        float bx = sbias[col], by = sbias[col + 1];
        float v0 = frelu(acc[mt][nt][0] + bx), v1 = frelu(acc[mt][nt][1] + by);
        float v2 = frelu(acc[mt][nt][2] + bx), v3 = frelu(acc[mt][nt][3] + by);
#pragma unroll
        for (int j = 0; j < NJ; j++) {
          float w0 = (MODE == 1) ? sWc2[col * 3 + j] : sWn2[col];
          float w1 = (MODE == 1) ? sWc2[(col + 1) * 3 + j] : sWn2[col + 1];
          part[mt][0][j] += v0 * w0 + v1 * w1;
          part[mt][1][j] += v2 * w0 + v3 * w1;
        }
      }
#pragma unroll
    for (int mt = 0; mt < 2; mt++)
#pragma unroll
      for (int rh = 0; rh < 2; rh++)
#pragma unroll
        for (int j = 0; j < NJ; j++) {
          float v = part[mt][rh][j];
          v += __shfl_xor_sync(0xffffffffu, v, 1);
          v += __shfl_xor_sync(0xffffffffu, v, 2);
          if (cx.qp == 0)
            atomicAdd(&outac[(cx.wm * 32 + mt * 16 + rh * 8 + cx.grp) * 4 + j], v);
        }
  }
  barsync();  // layer boundary
}

__global__ void __launch_bounds__(THREADS, 1) fused_mlp(Params p) {
  extern __shared__ char smem[];
  Ctx cx;
  cx.smem = smem;
  cx.tid = threadIdx.x;
  cx.lane = cx.tid & 31;
  const int wid = cx.tid >> 5;
  cx.wm = (wid >> 2) & 3; cx.wn = wid & 3;
  cx.lrow = cx.lane & 15; cx.lk = (cx.lane >> 4) << 3;
  cx.grp = cx.lane >> 2; cx.qp = cx.lane & 3;
  cx.act32 = smem_u32(smem + OFF_ACT);
  cx.wring32 = smem_u32(smem + OFF_WRING);
  cx.full32 = smem_u32(smem + OFF_FULL);
  cx.empty32 = smem_u32(smem + OFF_EMPTY);
  const uint32_t hbar32 = smem_u32(smem + OFF_HBAR);

  const int m0 = blockIdx.x * MT;
  __half* gh = g_h + (size_t)blockIdx.x * H_STRIDE;
  float* sx = (float*)(smem + OFF_SX);
  float* sB = (float*)(smem + OFF_SB);
  float* sb0 = (float*)(smem + OFF_BIAS);
  float* sb1 = (float*)(smem + OFF_BIAS + 1024);
  float* outac = (float*)(smem + OFF_OUTAC);
  __half* act = (__half*)(smem + OFF_ACT);

  if (cx.tid == 0) {
#pragma unroll
    for (int s = 0; s < 4; s++) {
      MBAR_INIT(cx.full32 + s * 8, 1);
      MBAR_INIT(cx.empty32 + s * 8, 16);
    }
    MBAR_INIT(hbar32, 1);
  }
  if (cx.tid < 384) {
    int m = cx.tid / 3, d = cx.tid - m * 3;
    sx[m * 4 + d] = p.x[(m0 + m) * 3 + d];
  }
  for (int i = cx.tid; i < 768; i += THREADS) sB[i] = p.B[i];
  if (cx.tid < 256) { sb0[cx.tid] = p.b0[cx.tid]; sb1[cx.tid] = p.b1[cx.tid]; }
  if (cx.tid < CTH) outac[cx.tid] = 0.0f;
  __syncthreads();  // all 544 threads; LAST full-block barrier

  if (wid == 16) {  // ---- producer warp ----
    if (cx.lane == 0) {
      for (int i = 0; i < N_CHUNKS; i++) {
        int s = i & 3;
        MBAR_WAIT(cx.empty32 + s * 8, 1 ^ ((i >> 2) & 1));  // first waits pass
        issue_bulk(cx.wring32 + s * CH_B, g_Wt + (size_t)i * CH_H, CH_B, cx.full32 + s * 8);
      }
    }
    return;
  }

  // ---- consumer (16 compute warps) ----
  int tbits = *p.t;
  float tval = (tbits >= 0 && tbits < (1 << 20)) ? (float)tbits : __int_as_float(tbits);
  const float tot = tval * (6000.0f / 512.0f);  // t / TAU

  // Layer 0: 9 chunks, on-the-fly features (double-buffered inside act region)
  {
    float acc[2][8][4];
#pragma unroll
    for (int a = 0; a < 2; a++)
#pragma unroll
      for (int b = 0; b < 8; b++)
#pragma unroll
        for (int d = 0; d < 4; d++) acc[a][b][d] = 0.0f;
    gen_feat(cx, 0, tot);
    for (int c = 0; c < L0_CHUNKS; c++) {
      barsync();  // feat buffer handoff
      const int s = c & 3;
      MBAR_WAIT(cx.full32 + s * 8, (c >> 2) & 1);
      chunk_mma(cx, cx.act32 + (c & 1) * FEAT_SZ, WS, 0, cx.wring32 + s * CH_B, acc);
      if (cx.lane == 0) MBAR_ARRIVE(cx.empty32 + s * 8);
      if (c + 1 < L0_CHUNKS) gen_feat(cx, c + 1, tot);
    }
    barsync();  // all feat reads done before epilogue overwrites act region
    // epilogue -> act (bias b0)
#pragma unroll
    for (int mt = 0; mt < 2; mt++) {
      const int r0 = cx.wm * 32 + mt * 16 + cx.grp;
#pragma unroll
      for (int nt = 0; nt < 8; nt++) {
        const int col = cx.wn * 64 + nt * 8 + cx.qp * 2;
        float bx = sb0[col], by = sb0[col + 1];
        *(uint32_t*)(act + r0 * AS + col) =
            pack2(frelu(acc[mt][nt][0] + bx), frelu(acc[mt][nt][1] + by));
        *(uint32_t*)(act + (r0 + 8) * AS + col) =
            pack2(frelu(acc[mt][nt][2] + bx), frelu(acc[mt][nt][3] + by));
      }
    }
    barsync();
  }

  // overlay head-final weights (sx/sB dead) + bias pipeline
  {
    float* sWc2 = (float*)(smem + OFF_WC2);
    float* sWn2 = (float*)(smem + OFF_WN2);
    for (int i = cx.tid; i < 768; i += CTH) sWc2[i] = p.Wc2[i];
    if (cx.tid < 256) sWn2[cx.tid] = p.Wn2[cx.tid];
  }

  if (cx.tid < 256) sb0[cx.tid] = p.b2[cx.tid];
  layerSq<0, false>(cx,  9, sb1, nullptr);  // l1 (b1)
  if (cx.tid < 256) sb1[cx.tid] = p.b3[cx.tid];
  layerSq<0, false>(cx, 13, sb0, nullptr);  // l2 (b2)
  if (cx.tid < 256) sb0[cx.tid] = p.b4[cx.tid];
  layerSq<0, false>(cx, 17, sb1, nullptr);  // l3 (b3)
  if (cx.tid < 256) sb1[cx.tid] = p.bc0[cx.tid];
  layerSq<0, true >(cx, 21, sb0, gh);       // l4 (b4) -> h to act + g_h
  if (cx.tid < 256) sb0[cx.tid] = p.bc1[cx.tid];
  layerSq<0, false>(cx, 25, sb1, nullptr);  // l5 (bc0), overwrites h in act
  if (cx.tid < 256) sb1[cx.tid] = p.bn0[cx.tid];
  layerSq<1, false>(cx, 29, sb0, nullptr);  // l6 (bc1), color dot
  if (cx.tid < 384) {
    int m = cx.tid / 3, j = cx.tid - m * 3;
    float v = outac[m * 4 + j];
    outac[m * 4 + j] = 0.0f;  // read-side zero for displacement head
    p.out[(m0 + m) * 3 + j] = tanhf(v + p.bc2[j]) * 0.5f;
  }
  // restore h from g_h into act (act reads finished at l6's internal barsync)
  if (cx.tid == 0) {
    asm volatile("fence.proxy.async;" ::: "memory");  // order l4's STGs before TMA read
    issue_bulk(cx.act32, gh, H_BYTES, hbar32);
  }
  MBAR_WAIT(hbar32, 0);
  barsync();
  if (cx.tid < 256) sb0[cx.tid] = p.bn1[cx.tid];
  layerSq<0, false>(cx, 33, sb1, nullptr);  // l7 (bn0)
  layerSq<2, false>(cx, 37, sb0, nullptr);  // l8 (bn1), displacement dot
  if (cx.tid < 128)
    p.out[3 * NPTS + m0 + cx.tid] = tanhf(outac[cx.tid * 4] + p.bn2[0]) * 0.1f;
}

extern "C" void kernel_launch(void* const* d_in, const int* in_sizes, int n_in,
                              void* d_out, int out_size) {
  int i = 0;
  const float* x = (const float*)d_in[i++];
  const float* B = (const float*)d_in[i++];
  const void* tp = nullptr;
  if (in_sizes[2] == 1) tp = d_in[i++];  // dict order: t at index 2
  const float *W[11], *bias[11];
  for (int j = 0; j < 11; j++) {
    W[j] = (const float*)d_in[i++];
    bias[j] = (const float*)d_in[i++];
  }
  if (!tp && i < n_in) tp = d_in[i++];

  cudaFuncSetAttribute(fused_mlp, cudaFuncAttributeMaxDynamicSharedMemorySize, SMEM_BYTES);

  constexpr int TOTAL = N_CHUNKS * CH_H;
  prep_weights<<<(TOTAL + 255) / 256, 256>>>(W[0], W[1], W[2], W[3], W[4],
                                             W[5], W[6], W[8], W[9]);

  Params p;
  p.x = x; p.B = B;
  p.b0 = bias[0]; p.b1 = bias[1]; p.b2 = bias[2]; p.b3 = bias[3]; p.b4 = bias[4];
  p.bc0 = bias[5]; p.bc1 = bias[6]; p.bc2 = bias[7];
  p.bn0 = bias[8]; p.bn1 = bias[9]; p.bn2 = bias[10];
  p.Wc2 = W[7]; p.Wn2 = W[10];
  p.t = (const int*)tp;
  p.out = (float*)d_out;

  fused_mlp<<<NPTS / MT, THREADS, SMEM_BYTES>>>(p);
}

// round 12
// speedup vs baseline: 1.1814x; 1.0110x over previous
#include <cuda_runtime.h>
#include <cuda_fp16.h>
#include <cstdint>

#define DEV __device__ __forceinline__

namespace {
constexpr int NPTS = 131072;
constexpr int MT = 128;       // points per CTA
constexpr int THREADS = 544;  // 16 compute warps (4Mx4N) + 1 producer warp
constexpr int CTH = 512;      // compute threads
constexpr int KC = 64;        // K chunk
constexpr int AS = 264;       // activation row stride (halves); 528B
constexpr int WS = 72;        // weight/feat row stride (halves); 144B
constexpr float TWO_PI = 6.2831853071795864769f;

constexpr int CH_H = 256 * WS;       // halves per weight chunk (18432)
constexpr uint32_t CH_B = CH_H * 2;  // 36864 bytes
constexpr int L0_CHUNKS = 8;         // K0 = 512 (sin/cos only; coords via epilogue)
constexpr int N_CHUNKS = L0_CHUNKS + 32;  // 40 flat chunks

constexpr int H_STRIDE = MT * AS;          // halves per CTA h tile (33792)
constexpr uint32_t H_BYTES = H_STRIDE * 2; // 67584

// SMEM map (bytes)
constexpr int OFF_ACT   = 0;                 // 128*264*2 = 67584 (in-place; feat overlaid)
constexpr int FEAT_SZ   = 128 * WS * 2;      // 18432 per feat buffer (x2, inside act region)
constexpr int OFF_WRING = 67584;             // 4 * 36864 = 147456
constexpr int OFF_UNION = 215040;            // L0: sx+sB | heads: Wc2+Wn2
constexpr int OFF_SX    = OFF_UNION;         // 2048
constexpr int OFF_SB    = OFF_UNION + 2048;  // 3072
constexpr int OFF_WC2   = OFF_UNION;         // 3072
constexpr int OFF_WN2   = OFF_UNION + 3072;  // 1024
constexpr int OFF_BIAS  = 220160;            // 2 x 1024
constexpr int OFF_OUTAC = 222208;            // 2048
constexpr int OFF_FULL  = 224256;            // 4 x 8
constexpr int OFF_EMPTY = 224288;            // 4 x 8
constexpr int OFF_HBAR  = 224320;            // 8
constexpr int OFF_TAIL  = 224384;            // 3 x 256 floats (W0 rows 0..2 = x,y,z)
constexpr int SMEM_BYTES = 227456;
}

// Weight images, flat: chunk i at g_Wt + i*CH_H.
__device__ __half g_Wt[(size_t)N_CHUNKS * CH_H];
// h spill (layer-4 output), per-CTA tile in padded AS layout
__device__ __half g_h[(size_t)(NPTS / MT) * H_STRIDE];

// ---------------- helpers ----------------
DEV uint32_t smem_u32(const void* p) {
  uint32_t a;
  asm("{ .reg .u64 t; cvta.to.shared.u64 t, %1; cvt.u32.u64 %0, t; }" : "=r"(a) : "l"(p));
  return a;
}
#define MBAR_INIT(mb, c) \
  asm volatile("mbarrier.init.shared.b64 [%0], %1;" :: "r"(mb), "r"(c) : "memory")
#define MBAR_ARRIVE(mb) \
  asm volatile("mbarrier.arrive.shared.b64 _, [%0];" :: "r"(mb) : "memory")
#define MBAR_WAIT(mb, ph) do {                                                        \
  uint32_t _m = (mb), _p = (uint32_t)(ph), _d;                                        \
  asm volatile("{ .reg .pred p; mbarrier.try_wait.parity.acquire.cta.shared::cta.b64 p, [%1], %2; selp.b32 %0,1,0,p; }" \
               : "=r"(_d) : "r"(_m), "r"(_p) : "memory");                             \
  if (!_d) {                                                                          \
    asm volatile("{ .reg .pred P1; WL%=: mbarrier.try_wait.parity.acquire.cta.shared::cta.b64 P1, [%0], %1, 0x989680; @P1 bra.uni WD%=; bra.uni WL%=; WD%=: }" \
                 :: "r"(_m), "r"(_p) : "memory");                                     \
  }                                                                                   \
} while (0)

DEV void barsync() { asm volatile("bar.sync 1, 512;" ::: "memory"); }  // compute warps only

DEV void issue_bulk(uint32_t dst32, const void* src, uint32_t nbytes, uint32_t mbar) {
  asm volatile("mbarrier.arrive.expect_tx.shared.b64 _, [%0], %1;"
               :: "r"(mbar), "r"(nbytes) : "memory");
  asm volatile(
      "cp.async.bulk.shared::cta.global.mbarrier::complete_tx::bytes [%0], [%1], %2, [%3];"
      :: "r"(dst32), "l"(src), "r"(nbytes), "r"(mbar) : "memory");
}

DEV void ldsm4(uint32_t* r, uint32_t addr) {
  asm volatile("ldmatrix.sync.aligned.m8n8.x4.shared.b16 {%0,%1,%2,%3}, [%4];"
               : "=r"(r[0]), "=r"(r[1]), "=r"(r[2]), "=r"(r[3]) : "r"(addr));
}
DEV void mma16816(float* d, const uint32_t* a, uint32_t b0, uint32_t b1) {
  asm volatile(
      "mma.sync.aligned.m16n8k16.row.col.f32.f16.f16.f32 "
      "{%0,%1,%2,%3}, {%4,%5,%6,%7}, {%8,%9}, {%0,%1,%2,%3};\n"
      : "+f"(d[0]), "+f"(d[1]), "+f"(d[2]), "+f"(d[3])
      : "r"(a[0]), "r"(a[1]), "r"(a[2]), "r"(a[3]), "r"(b0), "r"(b1));
}
DEV float frelu(float v) { return fmaxf(v, 0.0f); }
DEV uint32_t pack2(float a, float b) {
  __half2 h = __floats2half2_rn(a, b);
  return *reinterpret_cast<uint32_t*>(&h);
}

// ---------------- prep: pack weights into SMEM-image layout ----------------
// L0 image covers W0 rows 3..514 (sin/cos); rows 0..2 (coords) handled in-kernel.
__global__ void prep_weights(const float* W0, const float* W1, const float* W2,
                             const float* W3, const float* W4, const float* Wc0,
                             const float* Wc1, const float* Wn0, const float* Wn1) {
  int e = blockIdx.x * blockDim.x + threadIdx.x;
  constexpr int TOTAL = N_CHUNKS * CH_H;
  if (e >= TOTAL) return;
  int chunk = e / CH_H, r = e % CH_H, n = r / WS, kk = r % WS;
  float v = 0.0f;
  if (kk < KC) {
    if (chunk < L0_CHUNKS) {
      int k = chunk * KC + kk;           // 0..511 -> feature (sin|cos)
      v = W0[(k + 3) * 256 + n];
    } else {
      int c2 = chunk - L0_CHUNKS;
      int l = c2 >> 2, k = (c2 & 3) * KC + kk;
      const float* Ws[8] = {W1, W2, W3, W4, Wc0, Wc1, Wn0, Wn1};
      v = Ws[l][k * 256 + n];
    }
  }
  g_Wt[e] = __float2half(v);
}

// ---------------- fused kernel ----------------
struct Params {
  const float *x, *B, *W0;
  const float *b0, *b1, *b2, *b3, *b4, *bc0, *bc1, *bc2, *bn0, *bn1, *bn2;
  const float *Wc2, *Wn2;
  const int* t;
  float* out;
};

struct Ctx {
  char* smem;
  uint32_t act32, wring32, full32, empty32;
  int tid, wm, wn, lrow, lk, grp, qp, lane;
};

// Layer-0 feature chunk (K=512, branch-free): feature k' -> sin/cos of row j=k'&255.
DEV void gen_feat(const Ctx& cx, int c, float tot) {
  const float* sx = (const float*)(cx.smem + OFF_SX);
  const float* sB = (const float*)(cx.smem + OFF_SB);
  __half* dst = (__half*)(cx.smem + OFF_ACT + (c & 1) * FEAT_SZ);
  const int kk = cx.tid & 63;
  const int mb = cx.tid >> 6;  // 0..7; m = mb + i*8
  const int kg = c * KC + kk;  // 0..511
  const bool issin = kg < 256;
  const int j = kg & 255;
  const float Bx = sB[j], By = sB[256 + j], Bz = sB[512 + j];
  const float a = fminf(fmaxf(tot - (float)j, 0.0f), 1.0f);
#pragma unroll
  for (int i = 0; i < 16; i++) {
    const int m = mb + i * 8;
    float px = sx[m * 4] * Bx;
    px = fmaf(sx[m * 4 + 1], By, px);
    px = fmaf(sx[m * 4 + 2], Bz, px);
    float arg = px * TWO_PI;
    float qf = rintf(arg * 0.3183098861837907f);
    float r = fmaf(qf, -3.1414794921875f, arg);
    r = fmaf(qf, -1.1315941810607910156e-4f, r);
    r = fmaf(qf, -1.9841872589410058936e-9f, r);
    float v = issin ? __sinf(r) : __cosf(r);
    if (((int)qf) & 1) v = -v;
    dst[m * WS + kk] = __float2half(v * a);
  }
}

DEV void chunk_mma(const Ctx& cx, uint32_t aBase, int ast, int kb, uint32_t wslot,
                   float acc[2][8][4]) {
  const uint32_t aA0 = aBase + ((cx.wm * 32 + cx.lrow) * ast + kb + cx.lk) * 2;
  const uint32_t bA0 = wslot + ((cx.wn * 64 + cx.lrow) * WS + cx.lk) * 2;
#pragma unroll
  for (int ks = 0; ks < KC; ks += 16) {
    uint32_t a0[4], a1[4];
    ldsm4(a0, aA0 + ks * 2);
    ldsm4(a1, aA0 + ks * 2 + 16 * ast * 2);
#pragma unroll
    for (int np = 0; np < 4; np++) {
      uint32_t bb[4];
      ldsm4(bb, bA0 + ks * 2 + np * (16 * WS * 2));
      mma16816(acc[0][2 * np],     a0, bb[0], bb[2]);
      mma16816(acc[0][2 * np + 1], a0, bb[1], bb[3]);
      mma16816(acc[1][2 * np],     a1, bb[0], bb[2]);
      mma16816(acc[1][2 * np + 1], a1, bb[1], bb[3]);
    }
  }
}

// MODE 0: act in-place. MODE 1: dot Wc2 -> outac. MODE 2: dot Wn2 -> outac.
template <int MODE, bool SAVEH>
__device__ __noinline__ void layerSq(const Ctx& cx, int base, const float* sbias,
                                     __half* gh) {
  float* outac = (float*)(cx.smem + OFF_OUTAC);
  __half* act = (__half*)(cx.smem + OFF_ACT);

  float acc[2][8][4];
#pragma unroll
  for (int a = 0; a < 2; a++)
#pragma unroll
    for (int b = 0; b < 8; b++)
#pragma unroll
      for (int d = 0; d < 4; d++) acc[a][b][d] = 0.0f;

#pragma unroll
  for (int cp = 0; cp < 2; cp++) {
    const int g0 = base + 2 * cp, g1 = g0 + 1;
    const int s0 = g0 & 3, s1 = g1 & 3;
    MBAR_WAIT(cx.full32 + s0 * 8, (g0 >> 2) & 1);
    MBAR_WAIT(cx.full32 + s1 * 8, (g1 >> 2) & 1);
    chunk_mma(cx, cx.act32, AS, (2 * cp) * KC, cx.wring32 + s0 * CH_B, acc);
    if (cx.lane == 0) MBAR_ARRIVE(cx.empty32 + s0 * 8);
    chunk_mma(cx, cx.act32, AS, (2 * cp + 1) * KC, cx.wring32 + s1 * CH_B, acc);
    if (cx.lane == 0) MBAR_ARRIVE(cx.empty32 + s1 * 8);
  }
  barsync();  // in-place: all act reads done before epilogue writes

  if (MODE == 0) {
#pragma unroll
    for (int mt = 0; mt < 2; mt++) {
      const int r0 = cx.wm * 32 + mt * 16 + cx.grp;
#pragma unroll
      for (int nt = 0; nt < 8; nt++) {
        const int col = cx.wn * 64 + nt * 8 + cx.qp * 2;
        float bx = sbias[col], by = sbias[col + 1];
        uint32_t lo = pack2(frelu(acc[mt][nt][0] + bx), frelu(acc[mt][nt][1] + by));
        uint32_t hi = pack2(frelu(acc[mt][nt][2] + bx), frelu(acc[mt][nt][3] + by));
        *(uint32_t*)(act + r0 * AS + col) = lo;
        *(uint32_t*)(act + (r0 + 8) * AS + col) = hi;
        if (SAVEH) {
          *(uint32_t*)(gh + r0 * AS + col) = lo;
          *(uint32_t*)(gh + (r0 + 8) * AS + col) = hi;
        }
      }
    }
  } else {
    const float* sWc2 = (const float*)(cx.smem + OFF_WC2);
    const float* sWn2 = (const float*)(cx.smem + OFF_WN2);
    constexpr int NJ = (MODE == 1) ? 3 : 1;
    float part[2][2][NJ];
#pragma unroll
    for (int a = 0; a < 2; a++)
#pragma unroll
      for (int b = 0; b < 2; b++)
#pragma unroll
        for (int j = 0; j < NJ; j++) part[a][b][j] = 0.0f;
#pragma unroll
    for (int mt = 0; mt < 2; mt++)
#pragma unroll
      for (int nt = 0; nt < 8; nt++) {
        const int col = cx.wn * 64 + nt * 8 + cx.qp * 2;
        float bx = sbias[col], by = sbias[col + 1];
        float v0 = frelu(acc[mt][nt][0] + bx), v1 = frelu(acc[mt][nt][1] + by);
        float v2 = frelu(acc[mt][nt][2] + bx), v3 = frelu(acc[mt][nt][3] + by);
#pragma unroll
        for (int j = 0; j < NJ; j++) {
          float w0 = (MODE == 1) ? sWc2[col * 3 + j] : sWn2[col];
          float w1 = (MODE == 1) ? sWc2[(col + 1) * 3 + j] : sWn2[col + 1];
          part[mt][0][j] += v0 * w0 + v1 * w1;
          part[mt][1][j] += v2 * w0 + v3 * w1;
        }
      }
#pragma unroll
    for (int mt = 0; mt < 2; mt++)
#pragma unroll
      for (int rh = 0; rh < 2; rh++)
#pragma unroll
        for (int j = 0; j < NJ; j++) {
          float v = part[mt][rh][j];
          v += __shfl_xor_sync(0xffffffffu, v, 1);
          v += __shfl_xor_sync(0xffffffffu, v, 2);
          if (cx.qp == 0)
            atomicAdd(&outac[(cx.wm * 32 + mt * 16 + rh * 8 + cx.grp) * 4 + j], v);
        }
  }
  barsync();  // layer boundary
}

__global__ void __launch_bounds__(THREADS, 1) fused_mlp(Params p) {
  extern __shared__ char smem[];
  Ctx cx;
  cx.smem = smem;
  cx.tid = threadIdx.x;
  cx.lane = cx.tid & 31;
  const int wid = cx.tid >> 5;
  cx.wm = (wid >> 2) & 3; cx.wn = wid & 3;
  cx.lrow = cx.lane & 15; cx.lk = (cx.lane >> 4) << 3;
  cx.grp = cx.lane >> 2; cx.qp = cx.lane & 3;
  cx.act32 = smem_u32(smem + OFF_ACT);
  cx.wring32 = smem_u32(smem + OFF_WRING);
  cx.full32 = smem_u32(smem + OFF_FULL);
  cx.empty32 = smem_u32(smem + OFF_EMPTY);
  const uint32_t hbar32 = smem_u32(smem + OFF_HBAR);

  const int m0 = blockIdx.x * MT;
  __half* gh = g_h + (size_t)blockIdx.x * H_STRIDE;
  float* sx = (float*)(smem + OFF_SX);
  float* sB = (float*)(smem + OFF_SB);
  float* sb0 = (float*)(smem + OFF_BIAS);
  float* sb1 = (float*)(smem + OFF_BIAS + 1024);
  float* stail = (float*)(smem + OFF_TAIL);
  float* outac = (float*)(smem + OFF_OUTAC);
  __half* act = (__half*)(smem + OFF_ACT);

  if (cx.tid == 0) {
#pragma unroll
    for (int s = 0; s < 4; s++) {
      MBAR_INIT(cx.full32 + s * 8, 1);
      MBAR_INIT(cx.empty32 + s * 8, 16);
    }
    MBAR_INIT(hbar32, 1);
  }
  if (cx.tid < 384) {
    int m = cx.tid / 3, d = cx.tid - m * 3;
    sx[m * 4 + d] = p.x[(m0 + m) * 3 + d];
  }
  for (int i = cx.tid; i < 768; i += THREADS) {
    sB[i] = p.B[i];
    stail[i] = p.W0[i];  // W0 rows 0..2 (x,y,z), [d][256]
  }
  if (cx.tid < 256) { sb0[cx.tid] = p.b0[cx.tid]; sb1[cx.tid] = p.b1[cx.tid]; }
  if (cx.tid < CTH) outac[cx.tid] = 0.0f;
  __syncthreads();  // all 544 threads; LAST full-block barrier

  if (wid == 16) {  // ---- producer warp ----
    if (cx.lane == 0) {
      for (int i = 0; i < N_CHUNKS; i++) {
        int s = i & 3;
        MBAR_WAIT(cx.empty32 + s * 8, 1 ^ ((i >> 2) & 1));  // first waits pass
        issue_bulk(cx.wring32 + s * CH_B, g_Wt + (size_t)i * CH_H, CH_B, cx.full32 + s * 8);
      }
    }
    return;
  }

  // ---- consumer (16 compute warps) ----
  int tbits = *p.t;
  float tval = (tbits >= 0 && tbits < (1 << 20)) ? (float)tbits : __int_as_float(tbits);
  const float tot = tval * (6000.0f / 512.0f);  // t / TAU

  // Layer 0: 8 chunks (K=512 sin/cos), coords folded into epilogue
  {
    float acc[2][8][4];
#pragma unroll
    for (int a = 0; a < 2; a++)
#pragma unroll
      for (int b = 0; b < 8; b++)
#pragma unroll
        for (int d = 0; d < 4; d++) acc[a][b][d] = 0.0f;
    gen_feat(cx, 0, tot);
    for (int c = 0; c < L0_CHUNKS; c++) {
      barsync();  // feat buffer handoff
      const int s = c & 3;
      MBAR_WAIT(cx.full32 + s * 8, (c >> 2) & 1);
      chunk_mma(cx, cx.act32 + (c & 1) * FEAT_SZ, WS, 0, cx.wring32 + s * CH_B, acc);
      if (cx.lane == 0) MBAR_ARRIVE(cx.empty32 + s * 8);
      if (c + 1 < L0_CHUNKS) gen_feat(cx, c + 1, tot);
    }
    barsync();  // all feat reads done before epilogue overwrites act region
    // epilogue -> act: coord correction (+x,y,z @ W0 rows 0..2) then bias+relu
#pragma unroll
    for (int mt = 0; mt < 2; mt++) {
      const int r0 = cx.wm * 32 + mt * 16 + cx.grp;
      const float x0a = sx[r0 * 4], x1a = sx[r0 * 4 + 1], x2a = sx[r0 * 4 + 2];
      const float x0b = sx[(r0 + 8) * 4], x1b = sx[(r0 + 8) * 4 + 1], x2b = sx[(r0 + 8) * 4 + 2];
#pragma unroll
      for (int nt = 0; nt < 8; nt++) {
        const int col = cx.wn * 64 + nt * 8 + cx.qp * 2;
        float w00 = stail[col], w01 = stail[col + 1];
        float w10 = stail[256 + col], w11 = stail[256 + col + 1];
        float w20 = stail[512 + col], w21 = stail[512 + col + 1];
        float c0 = fmaf(x0a, w00, fmaf(x1a, w10, x2a * w20));
        float c1 = fmaf(x0a, w01, fmaf(x1a, w11, x2a * w21));
        float c2 = fmaf(x0b, w00, fmaf(x1b, w10, x2b * w20));
        float c3 = fmaf(x0b, w01, fmaf(x1b, w11, x2b * w21));
        float bx = sb0[col], by = sb0[col + 1];
        *(uint32_t*)(act + r0 * AS + col) =
            pack2(frelu(acc[mt][nt][0] + c0 + bx), frelu(acc[mt][nt][1] + c1 + by));
        *(uint32_t*)(act + (r0 + 8) * AS + col) =
            pack2(frelu(acc[mt][nt][2] + c2 + bx), frelu(acc[mt][nt][3] + c3 + by));
      }
    }
    barsync();
  }

  // overlay head-final weights (sx/sB dead) + bias pipeline
  {
    float* sWc2 = (float*)(smem + OFF_WC2);
    float* sWn2 = (float*)(smem + OFF_WN2);
    for (int i = cx.tid; i < 768; i += CTH) sWc2[i] = p.Wc2[i];
    if (cx.tid < 256) sWn2[cx.tid] = p.Wn2[cx.tid];
  }

  if (cx.tid < 256) sb0[cx.tid] = p.b2[cx.tid];
  layerSq<0, false>(cx,  8, sb1, nullptr);  // l1 (b1)
  if (cx.tid < 256) sb1[cx.tid] = p.b3[cx.tid];
  layerSq<0, false>(cx, 12, sb0, nullptr);  // l2 (b2)
  if (cx.tid < 256) sb0[cx.tid] = p.b4[cx.tid];
  layerSq<0, false>(cx, 16, sb1, nullptr);  // l3 (b3)
  if (cx.tid < 256) sb1[cx.tid] = p.bc0[cx.tid];
  layerSq<0, true >(cx, 20, sb0, gh);       // l4 (b4) -> h to act + g_h
  if (cx.tid < 256) sb0[cx.tid] = p.bc1[cx.tid];
  layerSq<0, false>(cx, 24, sb1, nullptr);  // l5 (bc0), overwrites h in act
  if (cx.tid < 256) sb1[cx.tid] = p.bn0[cx.tid];
  layerSq<1, false>(cx, 28, sb0, nullptr);  // l6 (bc1), color dot
  if (cx.tid < 384) {
    int m = cx.tid / 3, j = cx.tid - m * 3;
    float v = outac[m * 4 + j];
    outac[m * 4 + j] = 0.0f;  // read-side zero for displacement head
    p.out[(m0 + m) * 3 + j] = tanhf(v + p.bc2[j]) * 0.5f;
  }
  // restore h from g_h into act
  if (cx.tid == 0) {
    asm volatile("fence.proxy.async;" ::: "memory");  // order l4's STGs before TMA read
    issue_bulk(cx.act32, gh, H_BYTES, hbar32);
  }
  MBAR_WAIT(hbar32, 0);
  barsync();
  if (cx.tid < 256) sb0[cx.tid] = p.bn1[cx.tid];
  layerSq<0, false>(cx, 32, sb1, nullptr);  // l7 (bn0)
  layerSq<2, false>(cx, 36, sb0, nullptr);  // l8 (bn1), displacement dot
  if (cx.tid < 128)
    p.out[3 * NPTS + m0 + cx.tid] = tanhf(outac[cx.tid * 4] + p.bn2[0]) * 0.1f;
}

extern "C" void kernel_launch(void* const* d_in, const int* in_sizes, int n_in,
                              void* d_out, int out_size) {
  int i = 0;
  const float* x = (const float*)d_in[i++];
  const float* B = (const float*)d_in[i++];
  const void* tp = nullptr;
  if (in_sizes[2] == 1) tp = d_in[i++];  // dict order: t at index 2
  const float *W[11], *bias[11];
  for (int j = 0; j < 11; j++) {
    W[j] = (const float*)d_in[i++];
    bias[j] = (const float*)d_in[i++];
  }
  if (!tp && i < n_in) tp = d_in[i++];

  cudaFuncSetAttribute(fused_mlp, cudaFuncAttributeMaxDynamicSharedMemorySize, SMEM_BYTES);

  constexpr int TOTAL = N_CHUNKS * CH_H;
  prep_weights<<<(TOTAL + 255) / 256, 256>>>(W[0], W[1], W[2], W[3], W[4],
                                             W[5], W[6], W[8], W[9]);

  Params p;
  p.x = x; p.B = B; p.W0 = W[0];
  p.b0 = bias[0]; p.b1 = bias[1]; p.b2 = bias[2]; p.b3 = bias[3]; p.b4 = bias[4];
  p.bc0 = bias[5]; p.bc1 = bias[6]; p.bc2 = bias[7];
  p.bn0 = bias[8]; p.bn1 = bias[9]; p.bn2 = bias[10];
  p.Wc2 = W[7]; p.Wn2 = W[10];
  p.t = (const int*)tp;
  p.out = (float*)d_out;

  fused_mlp<<<NPTS / MT, THREADS, SMEM_BYTES>>>(p);
}

// round 13
// speedup vs baseline: 1.1893x; 1.0066x over previous
#include <cuda_runtime.h>
#include <cuda_fp16.h>
#include <cstdint>

#define DEV __device__ __forceinline__

namespace {
constexpr int NPTS = 131072;
constexpr int MT = 128;       // points per CTA
constexpr int THREADS = 544;  // 16 compute warps (4Mx4N) + 1 producer warp
constexpr int CTH = 512;      // compute threads
constexpr int KC = 64;        // K chunk
constexpr int AS = 264;       // activation row stride (halves); 528B
constexpr int WS = 72;        // weight/feat row stride (halves); 144B
constexpr float TWO_PI = 6.2831853071795864769f;

constexpr int CH_H = 256 * WS;       // halves per weight chunk (18432)
constexpr uint32_t CH_B = CH_H * 2;  // 36864 bytes
constexpr int L0_CHUNKS = 8;         // K0 = 512 (sin/cos only; coords via epilogue)
constexpr int N_CHUNKS = L0_CHUNKS + 32;  // 40 flat chunks

constexpr int H_STRIDE = MT * AS;          // halves per CTA h tile (33792)
constexpr uint32_t H_BYTES = H_STRIDE * 2; // 67584

// SMEM map (bytes)
constexpr int OFF_ACT   = 0;                 // 128*264*2 = 67584 (in-place; feat overlaid)
constexpr int FEAT_SZ   = 128 * WS * 2;      // 18432 per feat buffer (x2, inside act region)
constexpr int OFF_WRING = 67584;             // 4 * 36864 = 147456
constexpr int OFF_UNION = 215040;            // L0: sx+sB | heads: Wc2+Wn2
constexpr int OFF_SX    = OFF_UNION;         // 2048
constexpr int OFF_SB    = OFF_UNION + 2048;  // 3072
constexpr int OFF_WC2   = OFF_UNION;         // 3072
constexpr int OFF_WN2   = OFF_UNION + 3072;  // 1024
constexpr int OFF_BIAS  = 220160;            // 2 x 1024
constexpr int OFF_OUTAC = 222208;            // 2048
constexpr int OFF_FULL  = 224256;            // 4 x 8
constexpr int OFF_EMPTY = 224288;            // 4 x 8
constexpr int OFF_HBAR  = 224320;            // 8
constexpr int OFF_TAIL  = 224384;            // 3 x 256 floats (W0 rows 0..2)
constexpr int SMEM_BYTES = 227456;
}

// Weight images, flat: chunk i at g_Wt + i*CH_H.
__device__ __half g_Wt[(size_t)N_CHUNKS * CH_H];
// h spill (layer-4 output), per-CTA tile in padded AS layout
__device__ __half g_h[(size_t)(NPTS / MT) * H_STRIDE];

// ---------------- helpers ----------------
DEV uint32_t smem_u32(const void* p) {
  uint32_t a;
  asm("{ .reg .u64 t; cvta.to.shared.u64 t, %1; cvt.u32.u64 %0, t; }" : "=r"(a) : "l"(p));
  return a;
}
#define MBAR_INIT(mb, c) \
  asm volatile("mbarrier.init.shared.b64 [%0], %1;" :: "r"(mb), "r"(c) : "memory")
#define MBAR_ARRIVE(mb) \
  asm volatile("mbarrier.arrive.shared.b64 _, [%0];" :: "r"(mb) : "memory")
#define MBAR_WAIT(mb, ph) do {                                                        \
  uint32_t _m = (mb), _p = (uint32_t)(ph), _d;                                        \
  asm volatile("{ .reg .pred p; mbarrier.try_wait.parity.acquire.cta.shared::cta.b64 p, [%1], %2; selp.b32 %0,1,0,p; }" \
               : "=r"(_d) : "r"(_m), "r"(_p) : "memory");                             \
  if (!_d) {                                                                          \
    asm volatile("{ .reg .pred P1; WL%=: mbarrier.try_wait.parity.acquire.cta.shared::cta.b64 P1, [%0], %1, 0x989680; @P1 bra.uni WD%=; bra.uni WL%=; WD%=: }" \
                 :: "r"(_m), "r"(_p) : "memory");                                     \
  }                                                                                   \
} while (0)

DEV void barsync() { asm volatile("bar.sync 1, 512;" ::: "memory"); }  // compute warps only

DEV void issue_bulk(uint32_t dst32, const void* src, uint32_t nbytes, uint32_t mbar) {
  asm volatile("mbarrier.arrive.expect_tx.shared.b64 _, [%0], %1;"
               :: "r"(mbar), "r"(nbytes) : "memory");
  asm volatile(
      "cp.async.bulk.shared::cta.global.mbarrier::complete_tx::bytes [%0], [%1], %2, [%3];"
      :: "r"(dst32), "l"(src), "r"(nbytes), "r"(mbar) : "memory");
}

DEV void ldsm4(uint32_t* r, uint32_t addr) {
  asm volatile("ldmatrix.sync.aligned.m8n8.x4.shared.b16 {%0,%1,%2,%3}, [%4];"
               : "=r"(r[0]), "=r"(r[1]), "=r"(r[2]), "=r"(r[3]) : "r"(addr));
}
DEV void mma16816(float* d, const uint32_t* a, uint32_t b0, uint32_t b1) {
  asm volatile(
      "mma.sync.aligned.m16n8k16.row.col.f32.f16.f16.f32 "
      "{%0,%1,%2,%3}, {%4,%5,%6,%7}, {%8,%9}, {%0,%1,%2,%3};\n"
      : "+f"(d[0]), "+f"(d[1]), "+f"(d[2]), "+f"(d[3])
      : "r"(a[0]), "r"(a[1]), "r"(a[2]), "r"(a[3]), "r"(b0), "r"(b1));
}
DEV float frelu(float v) { return fmaxf(v, 0.0f); }
DEV uint32_t pack2(float a, float b) {
  __half2 h = __floats2half2_rn(a, b);
  return *reinterpret_cast<uint32_t*>(&h);
}

// ---------------- prep: pack weights into SMEM-image layout ----------------
__global__ void prep_weights(const float* W0, const float* W1, const float* W2,
                             const float* W3, const float* W4, const float* Wc0,
                             const float* Wc1, const float* Wn0, const float* Wn1) {
  int e = blockIdx.x * blockDim.x + threadIdx.x;
  constexpr int TOTAL = N_CHUNKS * CH_H;
  if (e >= TOTAL) return;
  int chunk = e / CH_H, r = e % CH_H, n = r / WS, kk = r % WS;
  float v = 0.0f;
  if (kk < KC) {
    if (chunk < L0_CHUNKS) {
      int k = chunk * KC + kk;           // 0..511 -> feature (sin|cos)
      v = W0[(k + 3) * 256 + n];
    } else {
      int c2 = chunk - L0_CHUNKS;
      int l = c2 >> 2, k = (c2 & 3) * KC + kk;
      const float* Ws[8] = {W1, W2, W3, W4, Wc0, Wc1, Wn0, Wn1};
      v = Ws[l][k * 256 + n];
    }
  }
  g_Wt[e] = __float2half(v);
}

// ---------------- fused kernel ----------------
struct Params {
  const float *x, *B, *W0;
  const float *b0, *b1, *b2, *b3, *b4, *bc0, *bc1, *bc2, *bn0, *bn1, *bn2;
  const float *Wc2, *Wn2;
  const int* t;
  float* out;
};

struct Ctx {
  char* smem;
  uint32_t act32, wring32, full32, empty32;
  int tid, wm, wn, lrow, lk, grp, qp, lane;
};

// Layer-0 feature chunk (K=512, branch-free).
DEV void gen_feat(const Ctx& cx, int c, float tot) {
  const float* sx = (const float*)(cx.smem + OFF_SX);
  const float* sB = (const float*)(cx.smem + OFF_SB);
  __half* dst = (__half*)(cx.smem + OFF_ACT + (c & 1) * FEAT_SZ);
  const int kk = cx.tid & 63;
  const int mb = cx.tid >> 6;  // 0..7; m = mb + i*8
  const int kg = c * KC + kk;  // 0..511
  const bool issin = kg < 256;
  const int j = kg & 255;
  const float Bx = sB[j], By = sB[256 + j], Bz = sB[512 + j];
  const float a = fminf(fmaxf(tot - (float)j, 0.0f), 1.0f);
#pragma unroll
  for (int i = 0; i < 16; i++) {
    const int m = mb + i * 8;
    float px = sx[m * 4] * Bx;
    px = fmaf(sx[m * 4 + 1], By, px);
    px = fmaf(sx[m * 4 + 2], Bz, px);
    float arg = px * TWO_PI;
    float qf = rintf(arg * 0.3183098861837907f);
    float r = fmaf(qf, -3.1414794921875f, arg);
    r = fmaf(qf, -1.1315941810607910156e-4f, r);
    r = fmaf(qf, -1.9841872589410058936e-9f, r);
    float v = issin ? __sinf(r) : __cosf(r);
    if (((int)qf) & 1) v = -v;
    dst[m * WS + kk] = __float2half(v * a);
  }
}

// Software-pipelined chunk: 16 stages (ks 0..3 x np 0..3). B fragment for stage
// s+1 and A fragments for ks+1 are loaded into parity buffers BEFORE stage s's
// MMAs, so LDSM latency is covered by MMA issue/tensor time (no WAR hazards).
DEV void chunk_mma(const Ctx& cx, uint32_t aBase, int ast, int kb, uint32_t wslot,
                   float acc[2][8][4]) {
  const uint32_t aA0 = aBase + ((cx.wm * 32 + cx.lrow) * ast + kb + cx.lk) * 2;
  const uint32_t bA0 = wslot + ((cx.wn * 64 + cx.lrow) * WS + cx.lk) * 2;
  uint32_t a0[2][4], a1[2][4], bb[2][4];
  ldsm4(a0[0], aA0);
  ldsm4(a1[0], aA0 + 16 * ast * 2);
  ldsm4(bb[0], bA0);
#pragma unroll
  for (int s = 0; s < 16; s++) {
    const int ks = s >> 2, np = s & 3;
    const int cur = s & 1, kpar = ks & 1;
    if (s + 1 < 16) {
      const int s2 = s + 1;
      const int ks2 = s2 >> 2, np2 = s2 & 3;
      ldsm4(bb[cur ^ 1], bA0 + ks2 * 32 + np2 * (16 * WS * 2));
    }
    if (np == 2 && ks + 1 < 4) {
      ldsm4(a0[kpar ^ 1], aA0 + (ks + 1) * 32);
      ldsm4(a1[kpar ^ 1], aA0 + (ks + 1) * 32 + 16 * ast * 2);
    }
    mma16816(acc[0][2 * np],     a0[kpar], bb[cur][0], bb[cur][2]);
    mma16816(acc[0][2 * np + 1], a0[kpar], bb[cur][1], bb[cur][3]);
    mma16816(acc[1][2 * np],     a1[kpar], bb[cur][0], bb[cur][2]);
    mma16816(acc[1][2 * np + 1], a1[kpar], bb[cur][1], bb[cur][3]);
  }
}

// MODE 0: act in-place. MODE 1: dot Wc2 -> outac. MODE 2: dot Wn2 -> outac.
template <int MODE, bool SAVEH>
__device__ __noinline__ void layerSq(const Ctx& cx, int base, const float* sbias,
                                     __half* gh) {
  float* outac = (float*)(cx.smem + OFF_OUTAC);
  __half* act = (__half*)(cx.smem + OFF_ACT);

  float acc[2][8][4];
#pragma unroll
  for (int a = 0; a < 2; a++)
#pragma unroll
    for (int b = 0; b < 8; b++)
#pragma unroll
      for (int d = 0; d < 4; d++) acc[a][b][d] = 0.0f;

#pragma unroll
  for (int cp = 0; cp < 2; cp++) {
    const int g0 = base + 2 * cp, g1 = g0 + 1;
    const int s0 = g0 & 3, s1 = g1 & 3;
    MBAR_WAIT(cx.full32 + s0 * 8, (g0 >> 2) & 1);
    MBAR_WAIT(cx.full32 + s1 * 8, (g1 >> 2) & 1);
    chunk_mma(cx, cx.act32, AS, (2 * cp) * KC, cx.wring32 + s0 * CH_B, acc);
    if (cx.lane == 0) MBAR_ARRIVE(cx.empty32 + s0 * 8);
    chunk_mma(cx, cx.act32, AS, (2 * cp + 1) * KC, cx.wring32 + s1 * CH_B, acc);
    if (cx.lane == 0) MBAR_ARRIVE(cx.empty32 + s1 * 8);
  }
  barsync();  // in-place: all act reads done before epilogue writes

  if (MODE == 0) {
#pragma unroll
    for (int mt = 0; mt < 2; mt++) {
      const int r0 = cx.wm * 32 + mt * 16 + cx.grp;
#pragma unroll
      for (int nt = 0; nt < 8; nt++) {
        const int col = cx.wn * 64 + nt * 8 + cx.qp * 2;
        float bx = sbias[col], by = sbias[col + 1];
        uint32_t lo = pack2(frelu(acc[mt][nt][0] + bx), frelu(acc[mt][nt][1] + by));
        uint32_t hi = pack2(frelu(acc[mt][nt][2] + bx), frelu(acc[mt][nt][3] + by));
        *(uint32_t*)(act + r0 * AS + col) = lo;
        *(uint32_t*)(act + (r0 + 8) * AS + col) = hi;
        if (SAVEH) {
          *(uint32_t*)(gh + r0 * AS + col) = lo;
          *(uint32_t*)(gh + (r0 + 8) * AS + col) = hi;
        }
      }
    }
  } else {
    const float* sWc2 = (const float*)(cx.smem + OFF_WC2);
    const float* sWn2 = (const float*)(cx.smem + OFF_WN2);
    constexpr int NJ = (MODE == 1) ? 3 : 1;
    float part[2][2][NJ];
#pragma unroll
    for (int a = 0; a < 2; a++)
#pragma unroll
      for (int b = 0; b < 2; b++)
#pragma unroll
        for (int j = 0; j < NJ; j++) part[a][b][j] = 0.0f;
#pragma unroll
    for (int mt = 0; mt < 2; mt++)
#pragma unroll
      for (int nt = 0; nt < 8; nt++) {
        const int col = cx.wn * 64 + nt * 8 + cx.qp * 2;
        float bx = sbias[col], by = sbias[col + 1];
        float v0 = frelu(acc[mt][nt][0] + bx), v1 = frelu(acc[mt][nt][1] + by);
        float v2 = frelu(acc[mt][nt][2] + bx), v3 = frelu(acc[mt][nt][3] + by);
#pragma unroll
        for (int j = 0; j < NJ; j++) {
          float w0 = (MODE == 1) ? sWc2[col * 3 + j] : sWn2[col];
          float w1 = (MODE == 1) ? sWc2[(col + 1) * 3 + j] : sWn2[col + 1];
          part[mt][0][j] += v0 * w0 + v1 * w1;
          part[mt][1][j] += v2 * w0 + v3 * w1;
        }
      }
#pragma unroll
    for (int mt = 0; mt < 2; mt++)
#pragma unroll
      for (int rh = 0; rh < 2; rh++)
#pragma unroll
        for (int j = 0; j < NJ; j++) {
          float v = part[mt][rh][j];
          v += __shfl_xor_sync(0xffffffffu, v, 1);
          v += __shfl_xor_sync(0xffffffffu, v, 2);
          if (cx.qp == 0)
            atomicAdd(&outac[(cx.wm * 32 + mt * 16 + rh * 8 + cx.grp) * 4 + j], v);
        }
  }
  barsync();  // layer boundary
}

__global__ void __launch_bounds__(THREADS, 1) fused_mlp(Params p) {
  extern __shared__ char smem[];
  Ctx cx;
  cx.smem = smem;
  cx.tid = threadIdx.x;
  cx.lane = cx.tid & 31;
  const int wid = cx.tid >> 5;
  cx.wm = (wid >> 2) & 3; cx.wn = wid & 3;
  cx.lrow = cx.lane & 15; cx.lk = (cx.lane >> 4) << 3;
  cx.grp = cx.lane >> 2; cx.qp = cx.lane & 3;
  cx.act32 = smem_u32(smem + OFF_ACT);
  cx.wring32 = smem_u32(smem + OFF_WRING);
  cx.full32 = smem_u32(smem + OFF_FULL);
  cx.empty32 = smem_u32(smem + OFF_EMPTY);
  const uint32_t hbar32 = smem_u32(smem + OFF_HBAR);

  const int m0 = blockIdx.x * MT;
  __half* gh = g_h + (size_t)blockIdx.x * H_STRIDE;
  float* sx = (float*)(smem + OFF_SX);
  float* sB = (float*)(smem + OFF_SB);
  float* sb0 = (float*)(smem + OFF_BIAS);
  float* sb1 = (float*)(smem + OFF_BIAS + 1024);
  float* stail = (float*)(smem + OFF_TAIL);
  float* outac = (float*)(smem + OFF_OUTAC);
  __half* act = (__half*)(smem + OFF_ACT);

  if (cx.tid == 0) {
#pragma unroll
    for (int s = 0; s < 4; s++) {
      MBAR_INIT(cx.full32 + s * 8, 1);
      MBAR_INIT(cx.empty32 + s * 8, 16);
    }
    MBAR_INIT(hbar32, 1);
  }
  if (cx.tid < 384) {
    int m = cx.tid / 3, d = cx.tid - m * 3;
    sx[m * 4 + d] = p.x[(m0 + m) * 3 + d];
  }
  for (int i = cx.tid; i < 768; i += THREADS) {
    sB[i] = p.B[i];
    stail[i] = p.W0[i];  // W0 rows 0..2 (x,y,z), [d][256]
  }
  if (cx.tid < 256) { sb0[cx.tid] = p.b0[cx.tid]; sb1[cx.tid] = p.b1[cx.tid]; }
  if (cx.tid < CTH) outac[cx.tid] = 0.0f;
  __syncthreads();  // all 544 threads; LAST full-block barrier

  if (wid == 16) {  // ---- producer warp ----
    if (cx.lane == 0) {
      for (int i = 0; i < N_CHUNKS; i++) {
        int s = i & 3;
        MBAR_WAIT(cx.empty32 + s * 8, 1 ^ ((i >> 2) & 1));  // first waits pass
        issue_bulk(cx.wring32 + s * CH_B, g_Wt + (size_t)i * CH_H, CH_B, cx.full32 + s * 8);
      }
    }
    return;
  }

  // ---- consumer (16 compute warps) ----
  int tbits = *p.t;
  float tval = (tbits >= 0 && tbits < (1 << 20)) ? (float)tbits : __int_as_float(tbits);
  const float tot = tval * (6000.0f / 512.0f);  // t / TAU

  // Layer 0: 8 chunks (K=512 sin/cos), coords folded into epilogue
  {
    float acc[2][8][4];
#pragma unroll
    for (int a = 0; a < 2; a++)
#pragma unroll
      for (int b = 0; b < 8; b++)
#pragma unroll
        for (int d = 0; d < 4; d++) acc[a][b][d] = 0.0f;
    gen_feat(cx, 0, tot);
    for (int c = 0; c < L0_CHUNKS; c++) {
      barsync();  // feat buffer handoff
      const int s = c & 3;
      MBAR_WAIT(cx.full32 + s * 8, (c >> 2) & 1);
      chunk_mma(cx, cx.act32 + (c & 1) * FEAT_SZ, WS, 0, cx.wring32 + s * CH_B, acc);
      if (cx.lane == 0) MBAR_ARRIVE(cx.empty32 + s * 8);
      if (c + 1 < L0_CHUNKS) gen_feat(cx, c + 1, tot);
    }
    barsync();  // all feat reads done before epilogue overwrites act region
    // epilogue -> act: coord correction (+x,y,z @ W0 rows 0..2) then bias+relu
#pragma unroll
    for (int mt = 0; mt < 2; mt++) {
      const int r0 = cx.wm * 32 + mt * 16 + cx.grp;
      const float x0a = sx[r0 * 4], x1a = sx[r0 * 4 + 1], x2a = sx[r0 * 4 + 2];
      const float x0b = sx[(r0 + 8) * 4], x1b = sx[(r0 + 8) * 4 + 1], x2b = sx[(r0 + 8) * 4 + 2];
#pragma unroll
      for (int nt = 0; nt < 8; nt++) {
        const int col = cx.wn * 64 + nt * 8 + cx.qp * 2;
        float w00 = stail[col], w01 = stail[col + 1];
        float w10 = stail[256 + col], w11 = stail[256 + col + 1];
        float w20 = stail[512 + col], w21 = stail[512 + col + 1];
        float c0 = fmaf(x0a, w00, fmaf(x1a, w10, x2a * w20));
        float c1 = fmaf(x0a, w01, fmaf(x1a, w11, x2a * w21));
        float c2 = fmaf(x0b, w00, fmaf(x1b, w10, x2b * w20));
        float c3 = fmaf(x0b, w01, fmaf(x1b, w11, x2b * w21));
        float bx = sb0[col], by = sb0[col + 1];
        *(uint32_t*)(act + r0 * AS + col) =
            pack2(frelu(acc[mt][nt][0] + c0 + bx), frelu(acc[mt][nt][1] + c1 + by));
        *(uint32_t*)(act + (r0 + 8) * AS + col) =
            pack2(frelu(acc[mt][nt][2] + c2 + bx), frelu(acc[mt][nt][3] + c3 + by));
      }
    }
    barsync();
  }

  // overlay head-final weights (sx/sB dead) + bias pipeline
  {
    float* sWc2 = (float*)(smem + OFF_WC2);
    float* sWn2 = (float*)(smem + OFF_WN2);
    for (int i = cx.tid; i < 768; i += CTH) sWc2[i] = p.Wc2[i];
    if (cx.tid < 256) sWn2[cx.tid] = p.Wn2[cx.tid];
  }

  if (cx.tid < 256) sb0[cx.tid] = p.b2[cx.tid];
  layerSq<0, false>(cx,  8, sb1, nullptr);  // l1 (b1)
  if (cx.tid < 256) sb1[cx.tid] = p.b3[cx.tid];
  layerSq<0, false>(cx, 12, sb0, nullptr);  // l2 (b2)
  if (cx.tid < 256) sb0[cx.tid] = p.b4[cx.tid];
  layerSq<0, false>(cx, 16, sb1, nullptr);  // l3 (b3)
  if (cx.tid < 256) sb1[cx.tid] = p.bc0[cx.tid];
  layerSq<0, true >(cx, 20, sb0, gh);       // l4 (b4) -> h to act + g_h
  if (cx.tid < 256) sb0[cx.tid] = p.bc1[cx.tid];
  layerSq<0, false>(cx, 24, sb1, nullptr);  // l5 (bc0), overwrites h in act
  if (cx.tid < 256) sb1[cx.tid] = p.bn0[cx.tid];
  layerSq<1, false>(cx, 28, sb0, nullptr);  // l6 (bc1), color dot
  if (cx.tid < 384) {
    int m = cx.tid / 3, j = cx.tid - m * 3;
    float v = outac[m * 4 + j];
    outac[m * 4 + j] = 0.0f;  // read-side zero for displacement head
    p.out[(m0 + m) * 3 + j] = tanhf(v + p.bc2[j]) * 0.5f;
  }
  // restore h from g_h into act
  if (cx.tid == 0) {
    asm volatile("fence.proxy.async;" ::: "memory");  // order l4's STGs before TMA read
    issue_bulk(cx.act32, gh, H_BYTES, hbar32);
  }
  MBAR_WAIT(hbar32, 0);
  barsync();
  if (cx.tid < 256) sb0[cx.tid] = p.bn1[cx.tid];
  layerSq<0, false>(cx, 32, sb1, nullptr);  // l7 (bn0)
  layerSq<2, false>(cx, 36, sb0, nullptr);  // l8 (bn1), displacement dot
  if (cx.tid < 128)
    p.out[3 * NPTS + m0 + cx.tid] = tanhf(outac[cx.tid * 4] + p.bn2[0]) * 0.1f;
}

extern "C" void kernel_launch(void* const* d_in, const int* in_sizes, int n_in,
                              void* d_out, int out_size) {
  int i = 0;
  const float* x = (const float*)d_in[i++];
  const float* B = (const float*)d_in[i++];
  const void* tp = nullptr;
  if (in_sizes[2] == 1) tp = d_in[i++];  // dict order: t at index 2
  const float *W[11], *bias[11];
  for (int j = 0; j < 11; j++) {
    W[j] = (const float*)d_in[i++];
    bias[j] = (const float*)d_in[i++];
  }
  if (!tp && i < n_in) tp = d_in[i++];

  cudaFuncSetAttribute(fused_mlp, cudaFuncAttributeMaxDynamicSharedMemorySize, SMEM_BYTES);

  constexpr int TOTAL = N_CHUNKS * CH_H;
  prep_weights<<<(TOTAL + 255) / 256, 256>>>(W[0], W[1], W[2], W[3], W[4],
                                             W[5], W[6], W[8], W[9]);

  Params p;
  p.x = x; p.B = B; p.W0 = W[0];
  p.b0 = bias[0]; p.b1 = bias[1]; p.b2 = bias[2]; p.b3 = bias[3]; p.b4 = bias[4];
  p.bc0 = bias[5]; p.bc1 = bias[6]; p.bc2 = bias[7];
  p.bn0 = bias[8]; p.bn1 = bias[9]; p.bn2 = bias[10];
  p.Wc2 = W[7]; p.Wn2 = W[10];
  p.t = (const int*)tp;
  p.out = (float*)d_out;

  fused_mlp<<<NPTS / MT, THREADS, SMEM_BYTES>>>(p);
}